// round 4
// baseline (speedup 1.0000x reference)
#include <cuda_runtime.h>
#include <cuda_bf16.h>

// LIFActivation fused single-kernel.
//
// out(x) = step function of x with 4 thresholds X1..X4 (n_spikes monotone in
// x for fixed scale). Each WARP redundantly computes the thresholds via a
// 9-ary ballot search (8 lanes per threshold) probing the EXACT reference
// fp32 sequence; the search hides under the warp's own in-flight loads.
// Search window: +/-4096 ulp around RN(s*k/4) (thresholds provably within a
// few ulp of s*k/4), bracket-verified with full-range fallback.

__device__ __forceinline__ int nspikes_ref(float x, float s) {
    float c = __fdiv_rn(fmaxf(x, 0.0f), s);  // IEEE RN div, exact ref semantics
    float v = 0.0f;
    int n = 0;
#pragma unroll
    for (int t = 0; t < 4; ++t) {
        v += c;
        if (v >= 1.0f) {  // H(v-1)==1 <=> v>=1
            v -= 1.0f;
            n += 1;
        }
    }
    return n;
}

// Warp-collective: lanes [8g, 8g+8) find smallest nonneg float bits u with
// nspikes_ref(u) >= g+1. Invariant: n(lo) < target (or lo==0), n(hi) >= target;
// answer = hi at convergence (hi-lo <= 1).
__device__ __forceinline__ void compute_thresholds(float s, float4& X, float4& V) {
    const unsigned FULL = 0xFFFFFFFFu;
    const unsigned FMAX = 0x7F7FFFFFu;
    int lane = threadIdx.x & 31;
    int grp  = lane >> 3;   // 0..3 -> target grp+1
    int sub  = lane & 7;    // probe index within group

    int target = grp + 1;
    float qs = 0.25f * s;                 // exact (power-of-2 scale)
    float center = (float)target * qs;    // ~= true threshold location
    unsigned cb = __float_as_uint(center);

    const unsigned W = 4096u;
    unsigned lo = (cb > W) ? cb - W : 0u;
    unsigned hi = (cb >= FMAX - W) ? FMAX : cb + W;

    bool lo_sat = nspikes_ref(__uint_as_float(lo), s) >= target;
    bool hi_sat = nspikes_ref(__uint_as_float(hi), s) >= target;
    bool feasible = true;
    if (lo_sat) {                 // threshold below window: bracket (0, lo]
        hi = lo; lo = 0u;         // n(0)=0 < target always
    } else if (!hi_sat) {         // threshold above window
        if (nspikes_ref(__uint_as_float(FMAX), s) >= target) {
            lo = hi; hi = FMAX;   // bracket (hi, FLT_MAX]
        } else {
            feasible = false;     // never spikes k times
            lo = hi;              // converged dummy
        }
    }

    // 9-ary search: 8 probes/group/iter; window case converges in 5 iters,
    // full-range fallback in <=11. Cap 12.
    for (int it = 0; it < 12; ++it) {
        bool conv = (hi - lo) <= 1u;
        if (__all_sync(FULL, conv)) break;
        unsigned long long range = (unsigned long long)(hi - lo);
        unsigned p = lo + (unsigned)(range * (unsigned long long)(sub + 1) / 9ull);
        bool sat = (!conv) && (nspikes_ref(__uint_as_float(p), s) >= target);
        unsigned bal = __ballot_sync(FULL, sat);
        if (!conv) {
            unsigned g = (bal >> (grp * 8)) & 0xFFu;
            if (g == 0u) {
                lo += (unsigned)(range * 8ull / 9ull);     // strictly increases
            } else {
                int j = __ffs((int)g) - 1;                 // first sat probe
                hi = lo + (unsigned)(range * (unsigned long long)(j + 1) / 9ull);
                if (j > 0)
                    lo += (unsigned)(range * (unsigned long long)j / 9ull);
            }
        }
    }

    float Xg = feasible ? __uint_as_float(hi) : __int_as_float(0x7F800000);
    X.x = __shfl_sync(FULL, Xg, 0);
    X.y = __shfl_sync(FULL, Xg, 8);
    X.z = __shfl_sync(FULL, Xg, 16);
    X.w = __shfl_sync(FULL, Xg, 24);
    // V_k = RN(k * RN(s/4)) == reference RN((k/4)*s) for k=1..4
    V.x = qs; V.y = 2.0f * qs; V.z = 3.0f * qs; V.w = 4.0f * qs;
}

__device__ __forceinline__ float lif_sel(float x, float4 X, float4 V) {
    float r = 0.0f;
    r = (x >= X.x) ? V.x : r;
    r = (x >= X.y) ? V.y : r;
    r = (x >= X.z) ? V.z : r;
    r = (x >= X.w) ? V.w : r;
    return r;   // NaN x -> all compares false -> 0, matches reference
}

__device__ __forceinline__ float4 lif_sel4(float4 xv, float4 X, float4 V) {
    float4 r;
    r.x = lif_sel(xv.x, X, V);
    r.y = lif_sel(xv.y, X, V);
    r.z = lif_sel(xv.z, X, V);
    r.w = lif_sel(xv.w, X, V);
    return r;
}

// 4 independent float4 streams per thread; loads issued before the search so
// the search runs inside their latency shadow.
__global__ void __launch_bounds__(256)
lif_fused_kernel(const float4* __restrict__ x,
                 const float*  __restrict__ scale_ptr,
                 float4* __restrict__ out, int n4, int quarter) {
    int i = blockIdx.x * blockDim.x + threadIdx.x;

    float s = fmaxf(__ldg(scale_ptr), 1e-12f);

    int i0 = i;
    int i1 = i + quarter;
    int i2 = i + 2 * quarter;
    int i3 = i + 3 * quarter;
    bool b0 = i0 < n4, b1 = i1 < n4, b2 = i2 < n4, b3 = i3 < n4;

    float4 a0, a1, a2, a3;
    if (b0) a0 = x[i0];
    if (b1) a1 = x[i1];
    if (b2) a2 = x[i2];
    if (b3) a3 = x[i3];

    float4 X, V;
    compute_thresholds(s, X, V);

    if (b0) out[i0] = lif_sel4(a0, X, V);
    if (b1) out[i1] = lif_sel4(a1, X, V);
    if (b2) out[i2] = lif_sel4(a2, X, V);
    if (b3) out[i3] = lif_sel4(a3, X, V);
}

extern "C" void kernel_launch(void* const* d_in, const int* in_sizes, int n_in,
                              void* d_out, int out_size) {
    const float* x     = (const float*)d_in[0];
    const float* scale = (const float*)d_in[1];
    float* out = (float*)d_out;

    int n  = out_size;       // 4096*8192, divisible by 16
    int n4 = n >> 2;         // float4 count
    int quarter = (n4 + 3) >> 2;

    const int threads = 256;
    int blocks = (quarter + threads - 1) / threads;
    lif_fused_kernel<<<blocks, threads>>>((const float4*)x, scale,
                                          (float4*)out, n4, quarter);
}

// round 5
// speedup vs baseline: 1.1909x; 1.1909x over previous
#include <cuda_runtime.h>
#include <cuda_bf16.h>

// LIFActivation, single fused kernel, per-BLOCK threshold search.
//
// out(x) is a 4-threshold step function of x (n_spikes monotone in x for
// fixed scale). Warp 0 of each block finds X1..X4 by a windowed 9-ary ballot
// search (8 lanes per threshold) probing the EXACT reference fp32 sequence,
// writes them to shared memory; all warps issue their global loads BEFORE the
// barrier so the search hides under load latency. Other warps pay only
// barrier + 2 LDS.

__device__ __forceinline__ int nspikes_ref(float x, float s) {
    float c = __fdiv_rn(fmaxf(x, 0.0f), s);  // IEEE RN div, exact ref semantics
    float v = 0.0f;
    int n = 0;
#pragma unroll
    for (int t = 0; t < 4; ++t) {
        v += c;
        if (v >= 1.0f) {  // H(v-1)==1 <=> v>=1
            v -= 1.0f;
            n += 1;
        }
    }
    return n;
}

// Warp-collective (warp 0 only): lanes [8g,8g+8) find the smallest
// nonnegative float bits u with nspikes_ref(u,s) >= g+1.
// Invariant: n(lo) < target (or lo==0), n(hi) >= target; answer = hi.
__device__ __forceinline__ void search_thresholds(float s, int lane,
                                                  float* sX, float* sV) {
    const unsigned FULL = 0xFFFFFFFFu;
    const unsigned FMAX = 0x7F7FFFFFu;
    int grp = lane >> 3;   // 0..3 -> target grp+1
    int sub = lane & 7;

    int target = grp + 1;
    float qs = 0.25f * s;                  // exact (power-of-2 scale)
    unsigned cb = __float_as_uint((float)target * qs);

    const unsigned W = 4096u;              // thresholds lie within a few ulp
    unsigned lo = (cb > W) ? cb - W : 0u;
    unsigned hi = (cb >= FMAX - W) ? FMAX : cb + W;

    bool lo_sat = nspikes_ref(__uint_as_float(lo), s) >= target;
    bool hi_sat = nspikes_ref(__uint_as_float(hi), s) >= target;
    bool feasible = true;
    if (lo_sat) {                 // threshold below window: bracket (0, lo]
        hi = lo; lo = 0u;         // n(0)=0 < target
    } else if (!hi_sat) {         // threshold above window
        if (nspikes_ref(__uint_as_float(FMAX), s) >= target) {
            lo = hi; hi = FMAX;
        } else {
            feasible = false;     // never reaches target spikes
            lo = hi;
        }
    }

    // 9-ary search: window case converges in 5 iters; full-range <=11. Cap 12.
    for (int it = 0; it < 12; ++it) {
        bool conv = (hi - lo) <= 1u;
        if (__all_sync(FULL, conv)) break;
        unsigned long long range = (unsigned long long)(hi - lo);
        unsigned p = lo + (unsigned)(range * (unsigned long long)(sub + 1) / 9ull);
        bool sat = (!conv) && (nspikes_ref(__uint_as_float(p), s) >= target);
        unsigned bal = __ballot_sync(FULL, sat);
        if (!conv) {
            unsigned g = (bal >> (grp * 8)) & 0xFFu;
            if (g == 0u) {
                lo += (unsigned)(range * 8ull / 9ull);
            } else {
                int j = __ffs((int)g) - 1;
                hi = lo + (unsigned)(range * (unsigned long long)(j + 1) / 9ull);
                if (j > 0)
                    lo += (unsigned)(range * (unsigned long long)j / 9ull);
            }
        }
    }

    if (sub == 0) {
        sX[grp] = feasible ? __uint_as_float(hi) : __int_as_float(0x7F800000);
        sV[grp] = (float)target * qs;  // RN(k*RN(s/4)) == RN((k/4)*s), k=1..4
    }
}

__device__ __forceinline__ float lif_sel(float x, float4 X, float4 V) {
    float r = 0.0f;
    r = (x >= X.x) ? V.x : r;
    r = (x >= X.y) ? V.y : r;
    r = (x >= X.z) ? V.z : r;
    r = (x >= X.w) ? V.w : r;
    return r;   // NaN -> all false -> 0, matches reference
}

__device__ __forceinline__ float4 lif_sel4(float4 xv, float4 X, float4 V) {
    float4 r;
    r.x = lif_sel(xv.x, X, V);
    r.y = lif_sel(xv.y, X, V);
    r.z = lif_sel(xv.z, X, V);
    r.w = lif_sel(xv.w, X, V);
    return r;
}

__global__ void __launch_bounds__(256)
lif_fused_kernel(const float4* __restrict__ x,
                 const float*  __restrict__ scale_ptr,
                 float4* __restrict__ out, int n4, int quarter) {
    __shared__ float sX[4];
    __shared__ float sV[4];

    int tid  = threadIdx.x;
    int i    = blockIdx.x * blockDim.x + tid;

    int i0 = i;
    int i1 = i + quarter;
    int i2 = i + 2 * quarter;
    int i3 = i + 3 * quarter;
    bool b0 = i0 < n4, b1 = i1 < n4, b2 = i2 < n4, b3 = i3 < n4;

    // Front-batched loads: in flight across the search + barrier.
    float4 a0, a1, a2, a3;
    if (b0) a0 = x[i0];
    if (b1) a1 = x[i1];
    if (b2) a2 = x[i2];
    if (b3) a3 = x[i3];

    if (tid < 32) {
        float s = fmaxf(__ldg(scale_ptr), 1e-12f);
        search_thresholds(s, tid, sX, sV);
    }
    __syncthreads();

    float4 X = make_float4(sX[0], sX[1], sX[2], sX[3]);  // broadcast LDS
    float4 V = make_float4(sV[0], sV[1], sV[2], sV[3]);

    if (b0) out[i0] = lif_sel4(a0, X, V);
    if (b1) out[i1] = lif_sel4(a1, X, V);
    if (b2) out[i2] = lif_sel4(a2, X, V);
    if (b3) out[i3] = lif_sel4(a3, X, V);
}

extern "C" void kernel_launch(void* const* d_in, const int* in_sizes, int n_in,
                              void* d_out, int out_size) {
    const float* x     = (const float*)d_in[0];
    const float* scale = (const float*)d_in[1];
    float* out = (float*)d_out;

    int n  = out_size;       // 4096*8192, divisible by 16
    int n4 = n >> 2;         // float4 count
    int quarter = (n4 + 3) >> 2;

    const int threads = 256;
    int blocks = (quarter + threads - 1) / threads;
    lif_fused_kernel<<<blocks, threads>>>((const float4*)x, scale,
                                          (float4*)out, n4, quarter);
}

// round 6
// speedup vs baseline: 1.1952x; 1.0036x over previous
#include <cuda_runtime.h>
#include <cuda_bf16.h>

// LIFActivation, single fused kernel, per-block threshold search (warp 0).
//
// out(x) is a 4-threshold step function of x. In exact arithmetic
// n = min(4, floor(4*relu(x)/s)), so each fp threshold lies within a few ulp
// of RN(k*s/4); warp 0 searches a +/-16-ulp window with a 9-ary ballot search
// probing the EXACT reference fp32 sequence (bracket-verified, falls back to
// a full-range search if the window misses -> correctness unconditional).
// Main path: 8 independent float4 streams/thread for MLP, select chain.

__device__ __forceinline__ int nspikes_ref(float x, float s) {
    float c = __fdiv_rn(fmaxf(x, 0.0f), s);  // IEEE RN div, exact ref semantics
    float v = 0.0f;
    int n = 0;
#pragma unroll
    for (int t = 0; t < 4; ++t) {
        v += c;
        if (v >= 1.0f) {  // H(v-1)==1 <=> v>=1
            v -= 1.0f;
            n += 1;
        }
    }
    return n;
}

// Warp-collective (warp 0 only): lanes [8g,8g+8) find the smallest
// nonnegative float bits u with nspikes_ref(u,s) >= g+1.
// Invariant: n(lo) < target (or lo==0), n(hi) >= target; answer = hi.
__device__ __forceinline__ void search_thresholds(float s, int lane,
                                                  float* sX, float* sV) {
    const unsigned FULL = 0xFFFFFFFFu;
    const unsigned FMAX = 0x7F7FFFFFu;
    int grp = lane >> 3;   // 0..3 -> target grp+1
    int sub = lane & 7;

    int target = grp + 1;
    float qs = 0.25f * s;                  // exact (power-of-2 scale)
    unsigned cb = __float_as_uint((float)target * qs);

    const unsigned W = 16u;                // threshold within a few ulp of center
    unsigned lo = (cb > W) ? cb - W : 0u;
    unsigned hi = (cb >= FMAX - W) ? FMAX : cb + W;

    bool lo_sat = nspikes_ref(__uint_as_float(lo), s) >= target;
    bool hi_sat = nspikes_ref(__uint_as_float(hi), s) >= target;
    bool feasible = true;
    if (lo_sat) {                 // threshold below window: bracket (0, lo]
        hi = lo; lo = 0u;         // n(0)=0 < target
    } else if (!hi_sat) {         // threshold above window
        if (nspikes_ref(__uint_as_float(FMAX), s) >= target) {
            lo = hi; hi = FMAX;
        } else {
            feasible = false;     // never reaches target spikes
            lo = hi;
        }
    }

    // 9-ary search: 32-ulp window converges in 2 iters; full-range fallback
    // <=11. Cap 12.
    for (int it = 0; it < 12; ++it) {
        bool conv = (hi - lo) <= 1u;
        if (__all_sync(FULL, conv)) break;
        unsigned long long range = (unsigned long long)(hi - lo);
        unsigned p = lo + (unsigned)(range * (unsigned long long)(sub + 1) / 9ull);
        bool sat = (!conv) && (nspikes_ref(__uint_as_float(p), s) >= target);
        unsigned bal = __ballot_sync(FULL, sat);
        if (!conv) {
            unsigned g = (bal >> (grp * 8)) & 0xFFu;
            if (g == 0u) {
                lo += (unsigned)(range * 8ull / 9ull);
            } else {
                int j = __ffs((int)g) - 1;
                hi = lo + (unsigned)(range * (unsigned long long)(j + 1) / 9ull);
                if (j > 0)
                    lo += (unsigned)(range * (unsigned long long)j / 9ull);
            }
        }
    }

    if (sub == 0) {
        sX[grp] = feasible ? __uint_as_float(hi) : __int_as_float(0x7F800000);
        sV[grp] = (float)target * qs;  // RN(k*RN(s/4)) == RN((k/4)*s), k=1..4
    }
}

__device__ __forceinline__ float lif_sel(float x, float4 X, float4 V) {
    float r = 0.0f;
    r = (x >= X.x) ? V.x : r;
    r = (x >= X.y) ? V.y : r;
    r = (x >= X.z) ? V.z : r;
    r = (x >= X.w) ? V.w : r;
    return r;   // NaN -> all false -> 0, matches reference
}

__device__ __forceinline__ float4 lif_sel4(float4 xv, float4 X, float4 V) {
    float4 r;
    r.x = lif_sel(xv.x, X, V);
    r.y = lif_sel(xv.y, X, V);
    r.z = lif_sel(xv.z, X, V);
    r.w = lif_sel(xv.w, X, V);
    return r;
}

// 8 independent float4 streams per thread, all loads front-batched before the
// search barrier so they are in flight during the search.
__global__ void __launch_bounds__(256)
lif_fused_kernel(const float4* __restrict__ x,
                 const float*  __restrict__ scale_ptr,
                 float4* __restrict__ out, int n4, int eighth) {
    __shared__ float sX[4];
    __shared__ float sV[4];

    int tid = threadIdx.x;
    int i   = blockIdx.x * blockDim.x + tid;

    int  idx[8];
    bool ok[8];
    float4 a[8];
#pragma unroll
    for (int k = 0; k < 8; ++k) {
        idx[k] = i + k * eighth;
        ok[k]  = idx[k] < n4;
    }
#pragma unroll
    for (int k = 0; k < 8; ++k)
        if (ok[k]) a[k] = x[idx[k]];

    if (tid < 32) {
        float s = fmaxf(__ldg(scale_ptr), 1e-12f);
        search_thresholds(s, tid, sX, sV);
    }
    __syncthreads();

    float4 X = make_float4(sX[0], sX[1], sX[2], sX[3]);  // broadcast LDS
    float4 V = make_float4(sV[0], sV[1], sV[2], sV[3]);

#pragma unroll
    for (int k = 0; k < 8; ++k)
        if (ok[k]) out[idx[k]] = lif_sel4(a[k], X, V);
}

extern "C" void kernel_launch(void* const* d_in, const int* in_sizes, int n_in,
                              void* d_out, int out_size) {
    const float* x     = (const float*)d_in[0];
    const float* scale = (const float*)d_in[1];
    float* out = (float*)d_out;

    int n  = out_size;       // 4096*8192
    int n4 = n >> 2;         // float4 count
    int eighth = (n4 + 7) >> 3;

    const int threads = 256;
    int blocks = (eighth + threads - 1) / threads;
    lif_fused_kernel<<<blocks, threads>>>((const float4*)x, scale,
                                          (float4*)out, n4, eighth);
}

// round 7
// speedup vs baseline: 1.2338x; 1.0324x over previous
#include <cuda_runtime.h>
#include <cuda_bf16.h>

// LIFActivation, single fused kernel, per-block threshold search (warp 0),
// 256-bit (v8) global loads/stores (sm_100+ PTX) for maximum stream width.
//
// out(x) is a 4-threshold step function of x. In exact arithmetic
// n = min(4, floor(4*relu(x)/s)), so each fp threshold lies within a few ulp
// of RN(k*s/4); warp 0 searches a +/-16-ulp window with a 9-ary ballot search
// probing the EXACT reference fp32 sequence (bracket-verified, full-range
// fallback -> correctness unconditional).

__device__ __forceinline__ int nspikes_ref(float x, float s) {
    float c = __fdiv_rn(fmaxf(x, 0.0f), s);  // IEEE RN div, exact ref semantics
    float v = 0.0f;
    int n = 0;
#pragma unroll
    for (int t = 0; t < 4; ++t) {
        v += c;
        if (v >= 1.0f) {  // H(v-1)==1 <=> v>=1
            v -= 1.0f;
            n += 1;
        }
    }
    return n;
}

// Warp-collective (warp 0 only): lanes [8g,8g+8) find the smallest
// nonnegative float bits u with nspikes_ref(u,s) >= g+1.
__device__ __forceinline__ void search_thresholds(float s, int lane,
                                                  float* sX, float* sV) {
    const unsigned FULL = 0xFFFFFFFFu;
    const unsigned FMAX = 0x7F7FFFFFu;
    int grp = lane >> 3;
    int sub = lane & 7;

    int target = grp + 1;
    float qs = 0.25f * s;                  // exact (power-of-2 scale)
    unsigned cb = __float_as_uint((float)target * qs);

    const unsigned W = 16u;
    unsigned lo = (cb > W) ? cb - W : 0u;
    unsigned hi = (cb >= FMAX - W) ? FMAX : cb + W;

    bool lo_sat = nspikes_ref(__uint_as_float(lo), s) >= target;
    bool hi_sat = nspikes_ref(__uint_as_float(hi), s) >= target;
    bool feasible = true;
    if (lo_sat) {                 // threshold below window: bracket (0, lo]
        hi = lo; lo = 0u;
    } else if (!hi_sat) {         // threshold above window
        if (nspikes_ref(__uint_as_float(FMAX), s) >= target) {
            lo = hi; hi = FMAX;
        } else {
            feasible = false;
            lo = hi;
        }
    }

    for (int it = 0; it < 12; ++it) {
        bool conv = (hi - lo) <= 1u;
        if (__all_sync(FULL, conv)) break;
        unsigned long long range = (unsigned long long)(hi - lo);
        unsigned p = lo + (unsigned)(range * (unsigned long long)(sub + 1) / 9ull);
        bool sat = (!conv) && (nspikes_ref(__uint_as_float(p), s) >= target);
        unsigned bal = __ballot_sync(FULL, sat);
        if (!conv) {
            unsigned g = (bal >> (grp * 8)) & 0xFFu;
            if (g == 0u) {
                lo += (unsigned)(range * 8ull / 9ull);
            } else {
                int j = __ffs((int)g) - 1;
                hi = lo + (unsigned)(range * (unsigned long long)(j + 1) / 9ull);
                if (j > 0)
                    lo += (unsigned)(range * (unsigned long long)j / 9ull);
            }
        }
    }

    if (sub == 0) {
        sX[grp] = feasible ? __uint_as_float(hi) : __int_as_float(0x7F800000);
        sV[grp] = (float)target * qs;  // RN(k*RN(s/4)) == RN((k/4)*s)
    }
}

// 256-bit global load/store (Blackwell sm_100+).
__device__ __forceinline__ void ldg_v8(const float* __restrict__ p, float* r) {
    asm("ld.global.nc.v8.f32 {%0,%1,%2,%3,%4,%5,%6,%7}, [%8];"
        : "=f"(r[0]), "=f"(r[1]), "=f"(r[2]), "=f"(r[3]),
          "=f"(r[4]), "=f"(r[5]), "=f"(r[6]), "=f"(r[7])
        : "l"(p));
}
__device__ __forceinline__ void stg_v8(float* __restrict__ p, const float* r) {
    asm volatile("st.global.v8.f32 [%0], {%1,%2,%3,%4,%5,%6,%7,%8};"
        :: "l"(p),
           "f"(r[0]), "f"(r[1]), "f"(r[2]), "f"(r[3]),
           "f"(r[4]), "f"(r[5]), "f"(r[6]), "f"(r[7])
        : "memory");
}

__device__ __forceinline__ float lif_sel(float x, float4 X, float4 V) {
    float r = 0.0f;
    r = (x >= X.x) ? V.x : r;
    r = (x >= X.y) ? V.y : r;
    r = (x >= X.z) ? V.z : r;
    r = (x >= X.w) ? V.w : r;
    return r;   // NaN -> all false -> 0, matches reference
}

// 4 independent 32-byte streams per thread, front-batched before the barrier.
__global__ void __launch_bounds__(256)
lif_fused_kernel(const float* __restrict__ x,
                 const float* __restrict__ scale_ptr,
                 float* __restrict__ out, int n8, int quarter) {
    __shared__ float sX[4];
    __shared__ float sV[4];

    int tid = threadIdx.x;
    int i   = blockIdx.x * blockDim.x + tid;

    int  idx[4];
    bool ok[4];
    float a[4][8];
#pragma unroll
    for (int k = 0; k < 4; ++k) {
        idx[k] = i + k * quarter;
        ok[k]  = idx[k] < n8;
    }
#pragma unroll
    for (int k = 0; k < 4; ++k)
        if (ok[k]) ldg_v8(x + (size_t)idx[k] * 8, a[k]);

    if (tid < 32) {
        float s = fmaxf(__ldg(scale_ptr), 1e-12f);
        search_thresholds(s, tid, sX, sV);
    }
    __syncthreads();

    float4 X = make_float4(sX[0], sX[1], sX[2], sX[3]);
    float4 V = make_float4(sV[0], sV[1], sV[2], sV[3]);

#pragma unroll
    for (int k = 0; k < 4; ++k) {
        if (ok[k]) {
            float r[8];
#pragma unroll
            for (int e = 0; e < 8; ++e) r[e] = lif_sel(a[k][e], X, V);
            stg_v8(out + (size_t)idx[k] * 8, r);
        }
    }
}

extern "C" void kernel_launch(void* const* d_in, const int* in_sizes, int n_in,
                              void* d_out, int out_size) {
    const float* x     = (const float*)d_in[0];
    const float* scale = (const float*)d_in[1];
    float* out = (float*)d_out;

    int n  = out_size;       // 4096*8192 = 2^25 (divisible by 32)
    int n8 = n >> 3;         // v8 (32-byte) chunk count
    int quarter = (n8 + 3) >> 2;

    const int threads = 256;
    int blocks = (quarter + threads - 1) / threads;
    lif_fused_kernel<<<blocks, threads>>>(x, scale, out, n8, quarter);
}